// round 3
// baseline (speedup 1.0000x reference)
#include <cuda_runtime.h>
#include <cstdint>

// Problem constants (static shapes from reference)
#define CC   64          // channels
#define CINN 66          // channels + 2 coord planes
#define HH   160
#define WW   256
#define LL   (HH * WW)   // 40960 pixels
#define TP   128         // pixels per tile
#define NINST 32         // 4 images * 8 instances
#define NPARAMS 8513

// param layout offsets
#define OFF_W0 0
#define OFF_W1 4224
#define OFF_W2 8320
#define OFF_B0 8384
#define OFF_B1 8448
#define OFF_B2 8512
#define MASK_BIAS_SHIFT 2.19f

// smem layout (floats), all section bases 16B aligned:
//  sWd0 : [c][2*o] duplicated weight pairs, c<66, stride 128 -> 8448
//  sWd1 : [c][2*o] duplicated, c<64, stride 128              -> 8192
//  sXH  : X tile [k][p] k<66 stride 128 (8448), later aliased
//         as H [o][p] o<64 stride 132 (8448)
//  sw2/sb0/sb1 : 64 each, sb2+pad : 4
#define SWD0_BASE 0
#define SWD1_BASE 8448
#define SXH_BASE  16640
#define SX_STRIDE 128
#define SH_STRIDE 132
#define MISC_BASE 25088
#define SMEM_FLOATS (25088 + 64*3 + 4)
#define SMEM_BYTES  (SMEM_FLOATS * 4)

__device__ __forceinline__ void fma2(unsigned long long& d, unsigned long long a, unsigned long long b) {
    asm("fma.rn.f32x2 %0, %1, %2, %0;" : "+l"(d) : "l"(a), "l"(b));
}
__device__ __forceinline__ float2 unpack2(unsigned long long v) {
    float2 f;
    asm("mov.b64 {%0,%1}, %2;" : "=f"(f.x), "=f"(f.y) : "l"(v));
    return f;
}

extern __shared__ __align__(16) float smem[];

__global__ __launch_bounds__(128, 2)
void condlane_fused_kernel(const float* __restrict__ x,
                           const float* __restrict__ params,
                           float* __restrict__ out)
{
    float* sWd0 = smem + SWD0_BASE;   // 66 x 128 (dup pairs)
    float* sWd1 = smem + SWD1_BASE;   // 64 x 128 (dup pairs)
    float* sXH  = smem + SXH_BASE;    // X: 66 x 128 / H: 64 x 132 (aliased)
    float* sw2  = smem + MISC_BASE;        // 64
    float* sb0  = smem + MISC_BASE + 64;   // 64
    float* sb1  = smem + MISC_BASE + 128;  // 64
    float* sb2  = smem + MISC_BASE + 192;  // 1

    const int tile = blockIdx.x;   // 0..319
    const int inst = blockIdx.y;   // 0..31
    const int img  = inst >> 3;    // 8 instances per image (static num_ins)
    const int tid  = threadIdx.x;  // 0..127

    const float* p = params + (size_t)inst * NPARAMS;

    // ---- W0 [64 o][66 c] -> sWd0[c][2o]=[2o+1]=w (duplicated pairs) ----
    for (int idx = tid; idx < 64 * 66; idx += 128) {
        int o = idx / 66;
        int c = idx - o * 66;
        float v = p[OFF_W0 + idx];
        *(float2*)(sWd0 + c * 128 + 2 * o) = make_float2(v, v);
    }
    // ---- W1 [64][64] -> sWd1 duplicated ----
    for (int idx = tid; idx < 64 * 64; idx += 128) {
        int o = idx >> 6;
        int c = idx & 63;
        float v = p[OFF_W1 + idx];
        *(float2*)(sWd1 + c * 128 + 2 * o) = make_float2(v, v);
    }
    if (tid < 64) {
        sw2[tid] = p[OFF_W2 + tid];
        sb0[tid] = p[OFF_B0 + tid];
        sb1[tid] = p[OFF_B1 + tid];
    }
    if (tid == 0) sb2[0] = p[OFF_B2] - MASK_BIAS_SHIFT;

    // ---- build X tile [66][128]: rows 0,1 coords, rows 2..65 channels ----
    const int l0 = tile * TP;            // tile start pixel
    const int ycoord = l0 >> 8;          // /WW, constant over tile
    const int xbase0 = l0 & (WW - 1);    // 0 or 128
    sXH[tid]       = (float)(xbase0 + tid);   // x-coords
    sXH[128 + tid] = (float)ycoord;           // y-coords
    {
        const float* xb = x + (size_t)img * CC * LL + l0;
        #pragma unroll
        for (int i = 0; i < 16; i++) {
            int f4 = i * 128 + tid;       // 0..2047
            int ch = f4 >> 5;             // 0..63
            int c4 = (f4 & 31) * 4;       // 0..124
            float4 v = *(const float4*)(xb + (size_t)ch * LL + c4);
            *(float4*)(sXH + (2 + ch) * SX_STRIDE + c4) = v;
        }
    }
    __syncthreads();

    // ---- thread tile: 8 output rows x 8 pixels ----
    const int tr = tid >> 4;      // 0..7 -> rows tr*8..tr*8+7
    const int tc = tid & 15;      // 0..15 -> px tc*4..+3 and 64+tc*4..+3
    const int ro = tr * 8;
    const int co = tc * 4;

    unsigned long long acc[8][4];   // [row][pixel-pair]
    #pragma unroll
    for (int i = 0; i < 8; i++)
        #pragma unroll
        for (int j = 0; j < 4; j++) acc[i][j] = 0ULL;

    // ======== GEMM1: hdn0 = W0 @ X  (K = 66) ========
    #pragma unroll 2
    for (int k = 0; k < CINN; k++) {
        ulonglong2 xa  = *(const ulonglong2*)(sXH + k * SX_STRIDE + co);
        ulonglong2 xbv = *(const ulonglong2*)(sXH + k * SX_STRIDE + 64 + co);
        const float* wk = sWd0 + k * 128 + 2 * ro;
        #pragma unroll
        for (int j = 0; j < 4; j++) {
            ulonglong2 wd = *(const ulonglong2*)(wk + 4 * j);  // rows ro+2j, ro+2j+1
            fma2(acc[2*j  ][0], wd.x, xa.x);
            fma2(acc[2*j  ][1], wd.x, xa.y);
            fma2(acc[2*j  ][2], wd.x, xbv.x);
            fma2(acc[2*j  ][3], wd.x, xbv.y);
            fma2(acc[2*j+1][0], wd.y, xa.x);
            fma2(acc[2*j+1][1], wd.y, xa.y);
            fma2(acc[2*j+1][2], wd.y, xbv.x);
            fma2(acc[2*j+1][3], wd.y, xbv.y);
        }
    }
    __syncthreads();   // all warps done reading X before H overwrites it

    // bias + relu -> sH (aliased onto X buffer)
    #pragma unroll
    for (int i = 0; i < 8; i++) {
        float b = sb0[ro + i];
        float r[8];
        float2 t;
        t = unpack2(acc[i][0]); r[0] = t.x; r[1] = t.y;
        t = unpack2(acc[i][1]); r[2] = t.x; r[3] = t.y;
        t = unpack2(acc[i][2]); r[4] = t.x; r[5] = t.y;
        t = unpack2(acc[i][3]); r[6] = t.x; r[7] = t.y;
        #pragma unroll
        for (int j = 0; j < 8; j++) {
            r[j] += b;
            r[j] = r[j] > 0.f ? r[j] : 0.f;
        }
        *(float4*)(sXH + (ro + i) * SH_STRIDE + co)      = make_float4(r[0], r[1], r[2], r[3]);
        *(float4*)(sXH + (ro + i) * SH_STRIDE + 64 + co) = make_float4(r[4], r[5], r[6], r[7]);
    }
    __syncthreads();

    // ======== GEMM2: hdn1 = W1 @ relu(hdn0)  (K = 64) ========
    #pragma unroll
    for (int i = 0; i < 8; i++)
        #pragma unroll
        for (int j = 0; j < 4; j++) acc[i][j] = 0ULL;

    #pragma unroll 2
    for (int k = 0; k < CC; k++) {
        ulonglong2 xa  = *(const ulonglong2*)(sXH + k * SH_STRIDE + co);
        ulonglong2 xbv = *(const ulonglong2*)(sXH + k * SH_STRIDE + 64 + co);
        const float* wk = sWd1 + k * 128 + 2 * ro;
        #pragma unroll
        for (int j = 0; j < 4; j++) {
            ulonglong2 wd = *(const ulonglong2*)(wk + 4 * j);
            fma2(acc[2*j  ][0], wd.x, xa.x);
            fma2(acc[2*j  ][1], wd.x, xa.y);
            fma2(acc[2*j  ][2], wd.x, xbv.x);
            fma2(acc[2*j  ][3], wd.x, xbv.y);
            fma2(acc[2*j+1][0], wd.y, xa.x);
            fma2(acc[2*j+1][1], wd.y, xa.y);
            fma2(acc[2*j+1][2], wd.y, xbv.x);
            fma2(acc[2*j+1][3], wd.y, xbv.y);
        }
    }
    __syncthreads();   // all reads of sH done before overwrite

    // bias + relu -> sH (reuse)
    #pragma unroll
    for (int i = 0; i < 8; i++) {
        float b = sb1[ro + i];
        float r[8];
        float2 t;
        t = unpack2(acc[i][0]); r[0] = t.x; r[1] = t.y;
        t = unpack2(acc[i][1]); r[2] = t.x; r[3] = t.y;
        t = unpack2(acc[i][2]); r[4] = t.x; r[5] = t.y;
        t = unpack2(acc[i][3]); r[6] = t.x; r[7] = t.y;
        #pragma unroll
        for (int j = 0; j < 8; j++) {
            r[j] += b;
            r[j] = r[j] > 0.f ? r[j] : 0.f;
        }
        *(float4*)(sXH + (ro + i) * SH_STRIDE + co)      = make_float4(r[0], r[1], r[2], r[3]);
        *(float4*)(sXH + (ro + i) * SH_STRIDE + 64 + co) = make_float4(r[4], r[5], r[6], r[7]);
    }
    __syncthreads();

    // ======== Layer 3: out[p] = w2 . hdn1[:,p] + b2 ========
    {
        float a3 = sb2[0];
        #pragma unroll
        for (int o = 0; o < CC; o++)
            a3 = fmaf(sw2[o], sXH[o * SH_STRIDE + tid], a3);
        out[(size_t)inst * LL + l0 + tid] = a3;
    }
}

extern "C" void kernel_launch(void* const* d_in, const int* in_sizes, int n_in,
                              void* d_out, int out_size)
{
    const float* x      = (const float*)d_in[0];   // [4,64,160,256] fp32
    const float* params = (const float*)d_in[1];   // [32,8513] fp32
    // d_in[2] = num_ins (static 8 per image, unused)
    float* out = (float*)d_out;                    // [1,32,160,256] fp32

    (void)in_sizes; (void)n_in; (void)out_size;

    cudaFuncSetAttribute(condlane_fused_kernel,
                         cudaFuncAttributeMaxDynamicSharedMemorySize, SMEM_BYTES);

    dim3 grid(LL / TP, NINST);   // 320 x 32
    condlane_fused_kernel<<<grid, 128, SMEM_BYTES>>>(x, params, out);
}

// round 4
// speedup vs baseline: 1.5446x; 1.5446x over previous
#include <cuda_runtime.h>
#include <cstdint>

// Problem constants (static shapes from reference)
#define CC   64          // channels
#define CINN 66          // channels + 2 coord planes
#define HH   160
#define WW   256
#define LL   (HH * WW)   // 40960 pixels
#define TP   256         // pixels per tile = one full image row
#define NTHREADS 512
#define NINST 32         // 4 images * 8 instances
#define NPARAMS 8513

// param layout offsets
#define OFF_W0 0
#define OFF_W1 4224
#define OFF_W2 8320
#define OFF_B0 8384
#define OFF_B1 8448
#define OFF_B2 8512
#define MASK_BIAS_SHIFT 2.19f

// smem layout (floats), all section bases multiples of 4 floats (16B aligned):
//  sW0t : transposed W0 [k<66][o<64], stride 68  -> 4488
//  sW1t : transposed W1 [k<64][o<64], stride 68  -> 4352  (base 4488)
//  sXH  : X [k<66][p<256] stride 256 -> 16896 (base 8840), aliased later
//         as H [o<64][p<256] stride 256
//  misc : sw2/sb0/sb1 64 each + sb2 + pad       (base 25736)
#define SWT_STRIDE 68
#define SW0T_BASE  0
#define SW1T_BASE  4488
#define SXH_BASE   8840
#define SROW       256
#define MISC_BASE  25736
#define SMEM_FLOATS (MISC_BASE + 64*3 + 4)
#define SMEM_BYTES  (SMEM_FLOATS * 4)

__device__ __forceinline__ unsigned long long pack2(float a, float b) {
    unsigned long long r;
    asm("mov.b64 %0, {%1,%2};" : "=l"(r) : "f"(a), "f"(b));
    return r;
}
__device__ __forceinline__ void fma2(unsigned long long& d, unsigned long long a, unsigned long long b) {
    asm("fma.rn.f32x2 %0, %1, %2, %0;" : "+l"(d) : "l"(a), "l"(b));
}
__device__ __forceinline__ float2 unpack2(unsigned long long v) {
    float2 f;
    asm("mov.b64 {%0,%1}, %2;" : "=f"(f.x), "=f"(f.y) : "l"(v));
    return f;
}

extern __shared__ __align__(16) float smem[];

__global__ __launch_bounds__(NTHREADS, 2)
void condlane_fused_kernel(const float* __restrict__ x,
                           const float* __restrict__ params,
                           float* __restrict__ out)
{
    float* sW0t = smem + SW0T_BASE;
    float* sW1t = smem + SW1T_BASE;
    float* sXH  = smem + SXH_BASE;
    float* sw2  = smem + MISC_BASE;
    float* sb0  = smem + MISC_BASE + 64;
    float* sb1  = smem + MISC_BASE + 128;
    float* sb2  = smem + MISC_BASE + 192;

    const int tile = blockIdx.x;   // 0..159  (image row)
    const int inst = blockIdx.y;   // 0..31
    const int img  = inst >> 3;    // 8 instances per image (static num_ins)
    const int tid  = threadIdx.x;  // 0..511

    const float* p = params + (size_t)inst * NPARAMS;

    // ---- W0 [64 o][66 c] -> sW0t[c][o] (transposed) ----
    for (int idx = tid; idx < 64 * 66; idx += NTHREADS) {
        int o = idx / 66;
        int c = idx - o * 66;
        sW0t[c * SWT_STRIDE + o] = p[OFF_W0 + idx];
    }
    // ---- W1 [64][64] -> sW1t[c][o] ----
    for (int idx = tid; idx < 64 * 64; idx += NTHREADS) {
        int o = idx >> 6;
        int c = idx & 63;
        sW1t[c * SWT_STRIDE + o] = p[OFF_W1 + idx];
    }
    if (tid < 64) {
        sw2[tid] = p[OFF_W2 + tid];
        sb0[tid] = p[OFF_B0 + tid];
        sb1[tid] = p[OFF_B1 + tid];
    }
    if (tid == 0) sb2[0] = p[OFF_B2] - MASK_BIAS_SHIFT;

    // ---- build X tile [66][256]: row 0 = x-coords (0..255), row 1 = y ----
    const int l0 = tile * TP;                // start pixel; tile == y coordinate
    if (tid < TP) {
        sXH[tid]        = (float)tid;        // x coord (full row, xbase = 0)
        sXH[SROW + tid] = (float)tile;       // y coord
    }
    {
        const float* xb = x + (size_t)img * CC * LL + l0;
        #pragma unroll
        for (int i = 0; i < 8; i++) {
            int f4 = i * NTHREADS + tid;     // 0..4095
            int ch = f4 >> 6;                // 0..63
            int c4 = (f4 & 63) * 4;          // 0..252
            float4 v = *(const float4*)(xb + (size_t)ch * LL + c4);
            *(float4*)(sXH + (2 + ch) * SROW + c4) = v;
        }
    }
    __syncthreads();

    // ---- warp tiling: warp w -> rows 8*(w&7) .. +7 ; pixel half (w>>3)*128 ----
    const int wid  = tid >> 5;
    const int lane = tid & 31;
    const int ro   = (wid & 7) * 8;
    const int pco  = (wid >> 3) * 128 + lane * 4;   // 4 consecutive pixels

    unsigned long long acc[8][2];   // [row][pixel-pair]
    #pragma unroll
    for (int i = 0; i < 8; i++) { acc[i][0] = 0ULL; acc[i][1] = 0ULL; }

    // ======== GEMM1: hdn0 = W0 @ X  (K = 66) ========
    #pragma unroll 2
    for (int k = 0; k < CINN; k++) {
        ulonglong2 xp = *(const ulonglong2*)(sXH + k * SROW + pco);
        const float* wk = sW0t + k * SWT_STRIDE + ro;
        float4 wa = *(const float4*)(wk);
        float4 wb = *(const float4*)(wk + 4);
        float w[8] = {wa.x, wa.y, wa.z, wa.w, wb.x, wb.y, wb.z, wb.w};
        #pragma unroll
        for (int r = 0; r < 8; r++) {
            unsigned long long wp = pack2(w[r], w[r]);
            fma2(acc[r][0], wp, xp.x);
            fma2(acc[r][1], wp, xp.y);
        }
    }
    __syncthreads();   // everyone done reading X before H overwrites it

    // bias + relu -> H (aliased onto X buffer, same stride)
    #pragma unroll
    for (int r = 0; r < 8; r++) {
        float b = sb0[ro + r];
        float2 t0 = unpack2(acc[r][0]);
        float2 t1 = unpack2(acc[r][1]);
        float4 v = make_float4(t0.x + b, t0.y + b, t1.x + b, t1.y + b);
        v.x = v.x > 0.f ? v.x : 0.f;
        v.y = v.y > 0.f ? v.y : 0.f;
        v.z = v.z > 0.f ? v.z : 0.f;
        v.w = v.w > 0.f ? v.w : 0.f;
        *(float4*)(sXH + (ro + r) * SROW + pco) = v;
    }
    __syncthreads();

    // ======== GEMM2: hdn1 = W1 @ relu(hdn0)  (K = 64) ========
    #pragma unroll
    for (int i = 0; i < 8; i++) { acc[i][0] = 0ULL; acc[i][1] = 0ULL; }

    #pragma unroll 2
    for (int k = 0; k < CC; k++) {
        ulonglong2 xp = *(const ulonglong2*)(sXH + k * SROW + pco);
        const float* wk = sW1t + k * SWT_STRIDE + ro;
        float4 wa = *(const float4*)(wk);
        float4 wb = *(const float4*)(wk + 4);
        float w[8] = {wa.x, wa.y, wa.z, wa.w, wb.x, wb.y, wb.z, wb.w};
        #pragma unroll
        for (int r = 0; r < 8; r++) {
            unsigned long long wp = pack2(w[r], w[r]);
            fma2(acc[r][0], wp, xp.x);
            fma2(acc[r][1], wp, xp.y);
        }
    }
    __syncthreads();   // all reads of H done before overwrite

    // bias + relu -> H (reuse)
    #pragma unroll
    for (int r = 0; r < 8; r++) {
        float b = sb1[ro + r];
        float2 t0 = unpack2(acc[r][0]);
        float2 t1 = unpack2(acc[r][1]);
        float4 v = make_float4(t0.x + b, t0.y + b, t1.x + b, t1.y + b);
        v.x = v.x > 0.f ? v.x : 0.f;
        v.y = v.y > 0.f ? v.y : 0.f;
        v.z = v.z > 0.f ? v.z : 0.f;
        v.w = v.w > 0.f ? v.w : 0.f;
        *(float4*)(sXH + (ro + r) * SROW + pco) = v;
    }
    __syncthreads();

    // ======== Layer 3: out[p] = w2 . hdn1[:,p] + b2 ========
    if (tid < TP) {
        float a3 = sb2[0];
        #pragma unroll
        for (int o = 0; o < CC; o++)
            a3 = fmaf(sw2[o], sXH[o * SROW + tid], a3);
        out[(size_t)inst * LL + l0 + tid] = a3;
    }
}

extern "C" void kernel_launch(void* const* d_in, const int* in_sizes, int n_in,
                              void* d_out, int out_size)
{
    const float* x      = (const float*)d_in[0];   // [4,64,160,256] fp32
    const float* params = (const float*)d_in[1];   // [32,8513] fp32
    // d_in[2] = num_ins (static 8 per image, unused)
    float* out = (float*)d_out;                    // [1,32,160,256] fp32

    (void)in_sizes; (void)n_in; (void)out_size;

    cudaFuncSetAttribute(condlane_fused_kernel,
                         cudaFuncAttributeMaxDynamicSharedMemorySize, SMEM_BYTES);

    dim3 grid(LL / TP, NINST);   // 160 x 32 = 5120 blocks
    condlane_fused_kernel<<<grid, NTHREADS, SMEM_BYTES>>>(x, params, out);
}

// round 5
// speedup vs baseline: 1.6651x; 1.0780x over previous
#include <cuda_runtime.h>
#include <cstdint>

// Problem constants (static shapes from reference)
#define CC   64          // channels
#define CINN 66          // channels + 2 coord planes
#define HH   160
#define WW   256
#define LL   (HH * WW)   // 40960 pixels
#define TP   256         // pixels per tile = one full image row
#define NTHREADS 512
#define NINST 32         // 4 images * 8 instances
#define NPARAMS 8513

// param layout offsets
#define OFF_W0 0
#define OFF_W1 4224
#define OFF_W2 8320
#define OFF_B0 8384
#define OFF_B1 8448
#define OFF_B2 8512
#define MASK_BIAS_SHIFT 2.19f

// smem layout (floats), all section bases multiples of 4 floats (16B aligned):
//  sW0t : transposed W0 [k<66][o<64], stride 68  -> 4488
//  sW1t : transposed W1 [k<64][o<64], stride 68  -> 4352  (base 4488)
//  sXH  : X [k<66][p<256] stride 256 -> 16896 (base 8840), aliased later
//         as H [o<64][p<256] stride 256
//  misc : sw2/sb0/sb1 64 each + sb2 + pad       (base 25736)
#define SWT_STRIDE 68
#define SW0T_BASE  0
#define SW1T_BASE  4488
#define SXH_BASE   8840
#define SROW       256
#define MISC_BASE  25736
#define SMEM_FLOATS (MISC_BASE + 64*3 + 4)
#define SMEM_BYTES  (SMEM_FLOATS * 4)

__device__ __forceinline__ unsigned long long pack2(float a, float b) {
    unsigned long long r;
    asm("mov.b64 %0, {%1,%2};" : "=l"(r) : "f"(a), "f"(b));
    return r;
}
__device__ __forceinline__ void fma2(unsigned long long& d, unsigned long long a, unsigned long long b) {
    asm("fma.rn.f32x2 %0, %1, %2, %0;" : "+l"(d) : "l"(a), "l"(b));
}
__device__ __forceinline__ float2 unpack2(unsigned long long v) {
    float2 f;
    asm("mov.b64 {%0,%1}, %2;" : "=f"(f.x), "=f"(f.y) : "l"(v));
    return f;
}

extern __shared__ __align__(16) float smem[];

__global__ __launch_bounds__(NTHREADS, 2)
void condlane_fused_kernel(const float* __restrict__ x,
                           const float* __restrict__ params,
                           float* __restrict__ out)
{
    float* sW0t = smem + SW0T_BASE;
    float* sW1t = smem + SW1T_BASE;
    float* sXH  = smem + SXH_BASE;
    float* sw2  = smem + MISC_BASE;
    float* sb0  = smem + MISC_BASE + 64;
    float* sb1  = smem + MISC_BASE + 128;
    float* sb2  = smem + MISC_BASE + 192;

    const int tile = blockIdx.x;   // 0..159  (image row)
    const int inst = blockIdx.y;   // 0..31
    const int img  = inst >> 3;    // 8 instances per image (static num_ins)
    const int tid  = threadIdx.x;  // 0..511

    const float* p = params + (size_t)inst * NPARAMS;

    // ---- W0 [64 o][66 c] -> sW0t[c][o] (transposed; adjacent rows adjacent) ----
    for (int idx = tid; idx < 64 * 66; idx += NTHREADS) {
        int o = idx / 66;
        int c = idx - o * 66;
        sW0t[c * SWT_STRIDE + o] = p[OFF_W0 + idx];
    }
    // ---- W1 [64][64] -> sW1t[c][o] ----
    for (int idx = tid; idx < 64 * 64; idx += NTHREADS) {
        int o = idx >> 6;
        int c = idx & 63;
        sW1t[c * SWT_STRIDE + o] = p[OFF_W1 + idx];
    }
    if (tid < 64) {
        sw2[tid] = p[OFF_W2 + tid];
        sb0[tid] = p[OFF_B0 + tid];
        sb1[tid] = p[OFF_B1 + tid];
    }
    if (tid == 0) sb2[0] = p[OFF_B2] - MASK_BIAS_SHIFT;

    // ---- build X tile [66][256]: row 0 = x-coords (0..255), row 1 = y ----
    const int l0 = tile * TP;                // start pixel; tile == y coordinate
    if (tid < TP) {
        sXH[tid]        = (float)tid;        // x coord (full row)
        sXH[SROW + tid] = (float)tile;       // y coord
    }
    {
        const float* xb = x + (size_t)img * CC * LL + l0;
        #pragma unroll
        for (int i = 0; i < 8; i++) {
            int f4 = i * NTHREADS + tid;     // 0..4095
            int ch = f4 >> 6;                // 0..63
            int c4 = (f4 & 63) * 4;          // 0..252
            float4 v = *(const float4*)(xb + (size_t)ch * LL + c4);
            *(float4*)(sXH + (2 + ch) * SROW + c4) = v;
        }
    }
    __syncthreads();

    // ---- warp tiling: warp w -> rows 8*(w&7) .. +7 ; pixel half (w>>3)*128 ----
    const int wid  = tid >> 5;
    const int lane = tid & 31;
    const int ro   = (wid & 7) * 8;                 // 8 rows = 4 row-pairs
    const int pco  = (wid >> 3) * 128 + lane * 4;   // 4 consecutive pixels

    // acc[pair r][pixel j] = (h[ro+2r][pj], h[ro+2r+1][pj])
    unsigned long long acc[4][4];
    #pragma unroll
    for (int i = 0; i < 4; i++)
        #pragma unroll
        for (int j = 0; j < 4; j++) acc[i][j] = 0ULL;

    // ======== GEMM1: hdn0 = W0 @ X  (K = 66) ========
    #pragma unroll 2
    for (int k = 0; k < CINN; k++) {
        float4 xv = *(const float4*)(sXH + k * SROW + pco);
        const float* wk = sW0t + k * SWT_STRIDE + ro;
        ulonglong2 w01 = *(const ulonglong2*)(wk);       // row-pairs (ro,ro+1),(ro+2,ro+3)
        ulonglong2 w23 = *(const ulonglong2*)(wk + 4);   // (ro+4,ro+5),(ro+6,ro+7)
        unsigned long long xp0 = pack2(xv.x, xv.x);
        unsigned long long xp1 = pack2(xv.y, xv.y);
        unsigned long long xp2 = pack2(xv.z, xv.z);
        unsigned long long xp3 = pack2(xv.w, xv.w);
        fma2(acc[0][0], w01.x, xp0); fma2(acc[0][1], w01.x, xp1);
        fma2(acc[0][2], w01.x, xp2); fma2(acc[0][3], w01.x, xp3);
        fma2(acc[1][0], w01.y, xp0); fma2(acc[1][1], w01.y, xp1);
        fma2(acc[1][2], w01.y, xp2); fma2(acc[1][3], w01.y, xp3);
        fma2(acc[2][0], w23.x, xp0); fma2(acc[2][1], w23.x, xp1);
        fma2(acc[2][2], w23.x, xp2); fma2(acc[2][3], w23.x, xp3);
        fma2(acc[3][0], w23.y, xp0); fma2(acc[3][1], w23.y, xp1);
        fma2(acc[3][2], w23.y, xp2); fma2(acc[3][3], w23.y, xp3);
    }
    __syncthreads();   // everyone done reading X before H overwrites it

    // bias + relu -> H (aliased onto X buffer)
    #pragma unroll
    for (int r = 0; r < 4; r++) {
        float blo = sb0[ro + 2 * r];
        float bhi = sb0[ro + 2 * r + 1];
        float2 t0 = unpack2(acc[r][0]);
        float2 t1 = unpack2(acc[r][1]);
        float2 t2 = unpack2(acc[r][2]);
        float2 t3 = unpack2(acc[r][3]);
        float4 vlo = make_float4(t0.x + blo, t1.x + blo, t2.x + blo, t3.x + blo);
        float4 vhi = make_float4(t0.y + bhi, t1.y + bhi, t2.y + bhi, t3.y + bhi);
        vlo.x = vlo.x > 0.f ? vlo.x : 0.f;  vlo.y = vlo.y > 0.f ? vlo.y : 0.f;
        vlo.z = vlo.z > 0.f ? vlo.z : 0.f;  vlo.w = vlo.w > 0.f ? vlo.w : 0.f;
        vhi.x = vhi.x > 0.f ? vhi.x : 0.f;  vhi.y = vhi.y > 0.f ? vhi.y : 0.f;
        vhi.z = vhi.z > 0.f ? vhi.z : 0.f;  vhi.w = vhi.w > 0.f ? vhi.w : 0.f;
        *(float4*)(sXH + (ro + 2 * r) * SROW + pco)     = vlo;
        *(float4*)(sXH + (ro + 2 * r + 1) * SROW + pco) = vhi;
    }
    __syncthreads();

    // ======== GEMM2: hdn1 = W1 @ relu(hdn0)  (K = 64) ========
    #pragma unroll
    for (int i = 0; i < 4; i++)
        #pragma unroll
        for (int j = 0; j < 4; j++) acc[i][j] = 0ULL;

    #pragma unroll 2
    for (int k = 0; k < CC; k++) {
        float4 xv = *(const float4*)(sXH + k * SROW + pco);
        const float* wk = sW1t + k * SWT_STRIDE + ro;
        ulonglong2 w01 = *(const ulonglong2*)(wk);
        ulonglong2 w23 = *(const ulonglong2*)(wk + 4);
        unsigned long long xp0 = pack2(xv.x, xv.x);
        unsigned long long xp1 = pack2(xv.y, xv.y);
        unsigned long long xp2 = pack2(xv.z, xv.z);
        unsigned long long xp3 = pack2(xv.w, xv.w);
        fma2(acc[0][0], w01.x, xp0); fma2(acc[0][1], w01.x, xp1);
        fma2(acc[0][2], w01.x, xp2); fma2(acc[0][3], w01.x, xp3);
        fma2(acc[1][0], w01.y, xp0); fma2(acc[1][1], w01.y, xp1);
        fma2(acc[1][2], w01.y, xp2); fma2(acc[1][3], w01.y, xp3);
        fma2(acc[2][0], w23.x, xp0); fma2(acc[2][1], w23.x, xp1);
        fma2(acc[2][2], w23.x, xp2); fma2(acc[2][3], w23.x, xp3);
        fma2(acc[3][0], w23.y, xp0); fma2(acc[3][1], w23.y, xp1);
        fma2(acc[3][2], w23.y, xp2); fma2(acc[3][3], w23.y, xp3);
    }
    __syncthreads();   // all reads of H done before overwrite

    // bias + relu -> H (reuse)
    #pragma unroll
    for (int r = 0; r < 4; r++) {
        float blo = sb1[ro + 2 * r];
        float bhi = sb1[ro + 2 * r + 1];
        float2 t0 = unpack2(acc[r][0]);
        float2 t1 = unpack2(acc[r][1]);
        float2 t2 = unpack2(acc[r][2]);
        float2 t3 = unpack2(acc[r][3]);
        float4 vlo = make_float4(t0.x + blo, t1.x + blo, t2.x + blo, t3.x + blo);
        float4 vhi = make_float4(t0.y + bhi, t1.y + bhi, t2.y + bhi, t3.y + bhi);
        vlo.x = vlo.x > 0.f ? vlo.x : 0.f;  vlo.y = vlo.y > 0.f ? vlo.y : 0.f;
        vlo.z = vlo.z > 0.f ? vlo.z : 0.f;  vlo.w = vlo.w > 0.f ? vlo.w : 0.f;
        vhi.x = vhi.x > 0.f ? vhi.x : 0.f;  vhi.y = vhi.y > 0.f ? vhi.y : 0.f;
        vhi.z = vhi.z > 0.f ? vhi.z : 0.f;  vhi.w = vhi.w > 0.f ? vhi.w : 0.f;
        *(float4*)(sXH + (ro + 2 * r) * SROW + pco)     = vlo;
        *(float4*)(sXH + (ro + 2 * r + 1) * SROW + pco) = vhi;
    }
    __syncthreads();

    // ======== Layer 3: out[p] = w2 . hdn1[:,p] + b2 ========
    if (tid < TP) {
        float a3 = sb2[0];
        #pragma unroll
        for (int o = 0; o < CC; o++)
            a3 = fmaf(sw2[o], sXH[o * SROW + tid], a3);
        out[(size_t)inst * LL + l0 + tid] = a3;
    }
}

extern "C" void kernel_launch(void* const* d_in, const int* in_sizes, int n_in,
                              void* d_out, int out_size)
{
    const float* x      = (const float*)d_in[0];   // [4,64,160,256] fp32
    const float* params = (const float*)d_in[1];   // [32,8513] fp32
    // d_in[2] = num_ins (static 8 per image, unused)
    float* out = (float*)d_out;                    // [1,32,160,256] fp32

    (void)in_sizes; (void)n_in; (void)out_size;

    cudaFuncSetAttribute(condlane_fused_kernel,
                         cudaFuncAttributeMaxDynamicSharedMemorySize, SMEM_BYTES);

    dim3 grid(LL / TP, NINST);   // 160 x 32 = 5120 blocks
    condlane_fused_kernel<<<grid, NTHREADS, SMEM_BYTES>>>(x, params, out);
}